// round 2
// baseline (speedup 1.0000x reference)
#include <cuda_runtime.h>
#include <math.h>

// Problem constants
#define Bb 32
#define Sс 1  /* unused guard */
#undef Sс
static const int B = 32;
static const int S = 512;
static const int R = 128;
static const int D = 64;
static const int E = 128;
static const int H = 256;
#define NROWS (32*512 + 128)   // B*S + R = 16512

// ---------------- scratch (static device globals; no runtime alloc) ----------
__device__ float g_emb[NROWS * 128];                 // (B*S + R, E)
__device__ float g_K[32 * 512 * 128];                // (B,S,E)
__device__ float g_Q[128 * 128];                     // (R,E)
__device__ float g_SC[32 * 128 * 512];               // scores -> exp(scores-max), (B,R,S)
__device__ float g_enc[32 * 128 * 64];               // (B,R,D)
__device__ float g_gi[2][128][768][32];              // [dir][t][row(3H)][batch]
__device__ float4 g_h[2][2][(256/4) * 32];           // [dir][parity][k4*32 + b]
__device__ int   g_bar[2];

// ---------------- 1) time embedding ----------------------------------------
__global__ void k_emb(const float* __restrict__ ts, const float* __restrict__ qt,
                      const float* __restrict__ w_per, const float* __restrict__ b_per,
                      const float* __restrict__ w_lin, const float* __restrict__ b_lin)
{
    int idx = blockIdx.x * blockDim.x + threadIdx.x;
    if (idx >= NROWS * 128) return;
    int row = idx >> 7;
    int e   = idx & 127;
    float t = (row < B * S) ? ts[row] : qt[row - B * S];
    float v;
    if (e == 0) v = fmaf(t, w_lin[0], b_lin[0]);
    else        v = sinf(fmaf(t, w_per[e - 1], b_per[e - 1]));
    g_emb[idx] = v;
}

// ---------------- 2) generic C = alpha * (A @ B^T) + bias ------------------
// A: [M,K] lda, Bm: [N,K] ldb, C: [M,N] ldc. 64x64 tile, k-chunk 16, 256 thr.
// All of M,N multiples of 64; K multiple of 16 (true for all uses here).
__global__ void __launch_bounds__(256)
k_gemm_nt(const float* __restrict__ Ag, const float* __restrict__ Bg,
          const float* __restrict__ bias, float* __restrict__ Cg,
          int Msz, int Nsz, int Ksz, int lda, int ldb, int ldc,
          long long strideA, long long strideB, long long strideC, float alpha)
{
    __shared__ float As[16][65];
    __shared__ float Bs[16][65];
    const float* A  = Ag + (long long)blockIdx.z * strideA;
    const float* Bm = Bg + (long long)blockIdx.z * strideB;
    float*       C  = Cg + (long long)blockIdx.z * strideC;
    int m0 = blockIdx.y * 64, n0 = blockIdx.x * 64;
    int tid = threadIdx.x;
    int tx = tid & 15, ty = tid >> 4;

    float acc[4][4];
#pragma unroll
    for (int i = 0; i < 4; i++)
#pragma unroll
        for (int j = 0; j < 4; j++) acc[i][j] = 0.f;

    for (int kc = 0; kc < Ksz; kc += 16) {
        int k = tid & 15;
        int v = tid >> 4; // 0..15
#pragma unroll
        for (int p = 0; p < 4; p++) {
            As[k][v + p * 16] = A[(long long)(m0 + v + p * 16) * lda + kc + k];
            Bs[k][v + p * 16] = Bm[(long long)(n0 + v + p * 16) * ldb + kc + k];
        }
        __syncthreads();
#pragma unroll
        for (int kk = 0; kk < 16; kk++) {
            float a[4], b[4];
#pragma unroll
            for (int i = 0; i < 4; i++) a[i] = As[kk][ty * 4 + i];
#pragma unroll
            for (int j = 0; j < 4; j++) b[j] = Bs[kk][tx * 4 + j];
#pragma unroll
            for (int i = 0; i < 4; i++)
#pragma unroll
                for (int j = 0; j < 4; j++) acc[i][j] = fmaf(a[i], b[j], acc[i][j]);
        }
        __syncthreads();
    }
#pragma unroll
    for (int i = 0; i < 4; i++) {
        int m = m0 + ty * 4 + i;
#pragma unroll
        for (int j = 0; j < 4; j++) {
            int n = n0 + tx * 4 + j;
            float v2 = acc[i][j] * alpha;
            if (bias) v2 += bias[n];
            C[(long long)m * ldc + n] = v2;
        }
    }
}

// ---------------- 3) per-(b,r) row: e = exp(score - rowmax) ----------------
__global__ void k_exp()
{
    int row = blockIdx.x;                 // 0 .. B*R-1
    float* p = g_SC + (long long)row * S;
    int tid = threadIdx.x;                // 128 threads
    float v[4];
    float m = -3.402823466e38f;
#pragma unroll
    for (int i = 0; i < 4; i++) { v[i] = p[tid + i * 128]; m = fmaxf(m, v[i]); }
#pragma unroll
    for (int off = 16; off > 0; off >>= 1)
        m = fmaxf(m, __shfl_xor_sync(0xffffffffu, m, off));
    __shared__ float sm[4];
    if ((tid & 31) == 0) sm[tid >> 5] = m;
    __syncthreads();
    m = fmaxf(fmaxf(sm[0], sm[1]), fmaxf(sm[2], sm[3]));
#pragma unroll
    for (int i = 0; i < 4; i++) p[tid + i * 128] = expf(v[i] - m);
}

// ---------------- 4) enc_in = (e @ mask*x) / (e @ mask) --------------------
__global__ void __launch_bounds__(256)
k_enc(const float* __restrict__ xv, const int* __restrict__ xm)
{
    __shared__ float Es[32][33];
    __shared__ float Xs[32][64];
    __shared__ float Ms[32][64];
    int b = blockIdx.x;
    int r0 = blockIdx.y * 32;
    int tid = threadIdx.x;
    int r  = tid >> 3;
    int d0 = (tid & 7) * 8;
    float accN[8], accD[8];
#pragma unroll
    for (int i = 0; i < 8; i++) { accN[i] = 0.f; accD[i] = 0.f; }

    for (int sc = 0; sc < S; sc += 32) {
        {
            int ss = tid & 31, rr = tid >> 5; // 8 rows / pass
#pragma unroll
            for (int p = 0; p < 4; p++)
                Es[rr + p * 8][ss] = g_SC[((long long)b * R + r0 + rr + p * 8) * S + sc + ss];
        }
        {
            int d = tid & 63, s0 = tid >> 6; // 4 s / pass
#pragma unroll
            for (int p = 0; p < 8; p++) {
                int ss = s0 + p * 4;
                long long gidx = ((long long)b * S + sc + ss) * D + d;
                int mk = xm[gidx];
                float x = xv[gidx];
                Xs[ss][d] = mk ? x : 0.f;
                Ms[ss][d] = mk ? 1.f : 0.f;
            }
        }
        __syncthreads();
#pragma unroll 4
        for (int ss = 0; ss < 32; ss++) {
            float e = Es[r][ss];
#pragma unroll
            for (int dd = 0; dd < 8; dd++) {
                accN[dd] = fmaf(e, Xs[ss][d0 + dd], accN[dd]);
                accD[dd] = fmaf(e, Ms[ss][d0 + dd], accD[dd]);
            }
        }
        __syncthreads();
    }
#pragma unroll
    for (int dd = 0; dd < 8; dd++)
        g_enc[((long long)b * R + r0 + r) * D + d0 + dd] = accN[dd] / accD[dd];
}

// ---------------- 5) gi[dir][t][row][b] = bih[row] + enc[b][tsrc] . Wih[row]
__global__ void __launch_bounds__(256)
k_gi(const float* __restrict__ Wf, const float* __restrict__ bf,
     const float* __restrict__ Wb, const float* __restrict__ bb)
{
    int rc  = blockIdx.x * 96;
    int t   = blockIdx.y;
    int dir = blockIdx.z;
    const float* W  = dir ? Wb : Wf;
    const float* bi = dir ? bb : bf;
    int tsrc = dir ? (R - 1 - t) : t;

    __shared__ float encs[32][65];
    __shared__ float Ws[96][64];
    int tid = threadIdx.x;
    {
        int d = tid & 63, b0 = tid >> 6;
#pragma unroll
        for (int p = 0; p < 8; p++) {
            int b = b0 + p * 4;
            encs[b][d] = g_enc[((long long)b * R + tsrc) * D + d];
        }
    }
    {
        int d = tid & 63, r0 = tid >> 6;
#pragma unroll
        for (int p = 0; p < 24; p++) {
            int rl = r0 + p * 4;
            Ws[rl][d] = W[(long long)(rc + rl) * D + d];
        }
    }
    __syncthreads();
    int b  = tid & 31;
    int rg = tid >> 5;
#pragma unroll 2
    for (int q = 0; q < 12; q++) {
        int rl = rg * 12 + q;
        float acc = bi[rc + rl];
#pragma unroll
        for (int d = 0; d < 64; d++)
            acc = fmaf(Ws[rl][d], encs[b][d], acc);
        g_gi[dir][t][rc + rl][b] = acc;
    }
}

// ---------------- 6) init barrier + h(0)=0 ---------------------------------
__global__ void k_init()
{
    int tid = blockIdx.x * 256 + threadIdx.x;
    if (tid < 2) g_bar[tid] = 0;
    if (tid < 2 * 2048) {
        int dir = tid >> 11;
        int i = tid & 2047;
        g_h[dir][0][i] = make_float4(0.f, 0.f, 0.f, 0.f);
    }
}

// ---------------- 7) persistent bidirectional GRU --------------------------
// grid = 128 CTAs (64 fwd, 64 bwd), 128 threads each. CTA owns 4 h-columns.
// Whh slice (12 rows) pinned in SMEM once; h (32KB) broadcast through L2
// every step; per-direction global flag barrier between steps.
__global__ void __launch_bounds__(128, 1)
k_gru(const float* __restrict__ Whh_f, const float* __restrict__ bhh_f,
      const float* __restrict__ Whh_b, const float* __restrict__ bhh_b,
      float* __restrict__ out)
{
    int bid = blockIdx.x;
    int dir = bid >> 6;
    int grp = bid & 63;
    int j0  = grp * 4;
    const float* Whh = dir ? Whh_b : Whh_f;
    const float* bhh = dir ? bhh_b : bhh_f;
    int tid = threadIdx.x;
    int w    = tid >> 5;   // warp -> column j0+w
    int lane = tid & 31;   // lane -> batch

    __shared__ float4 Ws[3][4][64];     // [gate][col][k4]  (12 KB)
    __shared__ float4 hs[64 * 32];      // h[t]: [k4][batch] (32 KB)
    __shared__ float  hn_s[32][4];

    // load Whh slice once (12 rows of 256 floats)
    for (int i = tid; i < 12 * 64; i += 128) {
        int rowi = i >> 6;     // 0..11
        int k4   = i & 63;
        int g = rowi >> 2;     // gate
        int c = rowi & 3;      // column
        Ws[g][c][k4] = reinterpret_cast<const float4*>(
            Whh + ((long long)(g * H + j0 + c)) * H)[k4];
    }
    float br = bhh[0 * H + j0 + w];
    float bz = bhh[1 * H + j0 + w];
    float bn = bhh[2 * H + j0 + w];
    __syncthreads();

    volatile int* barp = (volatile int*)&g_bar[dir];

    for (int t = 0; t < R; t++) {
        int par = t & 1;
        // gi for this step (independent of barrier data)
        float gir = __ldcg(&g_gi[dir][t][0 * H + j0 + w][lane]);
        float giz = __ldcg(&g_gi[dir][t][1 * H + j0 + w][lane]);
        float gin = __ldcg(&g_gi[dir][t][2 * H + j0 + w][lane]);
        // h[t] -> smem (L2-only loads: ping-pong buffer must bypass L1)
        const float4* hg = &g_h[dir][par][0];
        for (int i = tid; i < 2048; i += 128) hs[i] = __ldcg(&hg[i]);
        __syncthreads();

        float ar = 0.f, az = 0.f, an = 0.f;
#pragma unroll 16
        for (int k4 = 0; k4 < 64; k4++) {
            float4 hv = hs[k4 * 32 + lane];
            float4 wr = Ws[0][w][k4];
            float4 wz = Ws[1][w][k4];
            float4 wn = Ws[2][w][k4];
            ar = fmaf(wr.x, hv.x, ar); ar = fmaf(wr.y, hv.y, ar);
            ar = fmaf(wr.z, hv.z, ar); ar = fmaf(wr.w, hv.w, ar);
            az = fmaf(wz.x, hv.x, az); az = fmaf(wz.y, hv.y, az);
            az = fmaf(wz.z, hv.z, az); az = fmaf(wz.w, hv.w, az);
            an = fmaf(wn.x, hv.x, an); an = fmaf(wn.y, hv.y, an);
            an = fmaf(wn.z, hv.z, an); an = fmaf(wn.w, hv.w, an);
        }
        // old h for this (batch, column)
        float4 ho4 = hs[(j0 >> 2) * 32 + lane];
        float hold = (w == 0) ? ho4.x : (w == 1) ? ho4.y : (w == 2) ? ho4.z : ho4.w;

        float rr = 1.f / (1.f + expf(-(gir + ar + br)));
        float zz = 1.f / (1.f + expf(-(giz + az + bz)));
        float nn = tanhf(gin + rr * (an + bn));
        float hn = (1.f - zz) * nn + zz * hold;

        int tout = dir ? (R - 1 - t) : t;
        out[((long long)lane * R + tout) * (2 * H) + dir * H + j0 + w] = hn;

        hn_s[lane][w] = hn;
        __syncthreads();

        if (t < R - 1) {
            if (tid < 32) {
                float4 v = make_float4(hn_s[tid][0], hn_s[tid][1],
                                       hn_s[tid][2], hn_s[tid][3]);
                g_h[dir][par ^ 1][(j0 >> 2) * 32 + tid] = v;
                __threadfence();
            }
            __syncthreads();
            if (tid == 0) {
                atomicAdd(&g_bar[dir], 1);
                int target = 64 * (t + 1);
                while (*barp < target) { }
            }
            __syncthreads();
        }
    }
}

// ---------------- launcher -------------------------------------------------
extern "C" void kernel_launch(void* const* d_in, const int* in_sizes, int n_in,
                              void* d_out, int out_size)
{
    const float* x_vals     = (const float*)d_in[0];
    const int*   x_mask     = (const int*)  d_in[1];
    const float* time_steps = (const float*)d_in[2];
    const float* query_t    = (const float*)d_in[3];
    const float* Wq         = (const float*)d_in[4];
    const float* bq         = (const float*)d_in[5];
    const float* Wk         = (const float*)d_in[6];
    const float* bk         = (const float*)d_in[7];
    const float* w_per      = (const float*)d_in[8];
    const float* b_per      = (const float*)d_in[9];
    const float* w_lin      = (const float*)d_in[10];
    const float* b_lin      = (const float*)d_in[11];
    const float* Wih_f      = (const float*)d_in[12];
    const float* Whh_f      = (const float*)d_in[13];
    const float* bih_f      = (const float*)d_in[14];
    const float* bhh_f      = (const float*)d_in[15];
    const float* Wih_b      = (const float*)d_in[16];
    const float* Whh_b      = (const float*)d_in[17];
    const float* bih_b      = (const float*)d_in[18];
    const float* bhh_b      = (const float*)d_in[19];
    float* out = (float*)d_out;

    float *p_emb, *p_K, *p_Q, *p_SC;
    cudaGetSymbolAddress((void**)&p_emb, g_emb);
    cudaGetSymbolAddress((void**)&p_K,   g_K);
    cudaGetSymbolAddress((void**)&p_Q,   g_Q);
    cudaGetSymbolAddress((void**)&p_SC,  g_SC);

    // 1) embeddings for all B*S key rows + R query rows
    k_emb<<<(NROWS * 128 + 255) / 256, 256>>>(time_steps, query_t,
                                              w_per, b_per, w_lin, b_lin);
    // 2) K = emb_k @ Wk^T + bk   (M=B*S, N=E, K=E)
    {
        dim3 g(E / 64, (B * S) / 64, 1);
        k_gemm_nt<<<g, 256>>>(p_emb, Wk, bk, p_K, B * S, E, E, E, E, E,
                              0, 0, 0, 1.0f);
    }
    // 3) Q = emb_q @ Wq^T + bq   (M=R, N=E, K=E)
    {
        dim3 g(E / 64, R / 64, 1);
        k_gemm_nt<<<g, 256>>>(p_emb + (long long)B * S * E, Wq, bq, p_Q,
                              R, E, E, E, E, E, 0, 0, 0, 1.0f);
    }
    // 4) scores[b] = Q @ K_b^T / sqrt(E)   (batched over z)
    {
        dim3 g(S / 64, R / 64, B);
        k_gemm_nt<<<g, 256>>>(p_Q, p_K, nullptr, p_SC, R, S, E, E, E, S,
                              0, (long long)S * E, (long long)R * S,
                              0.08838834764831845f);
    }
    // 5) exp(score - rowmax) in place
    k_exp<<<B * R, 128>>>();
    // 6) enc_in = (e @ mx) / (e @ m)
    {
        dim3 g(B, R / 32);
        k_enc<<<g, 256>>>(x_vals, x_mask);
    }
    // 7) gi for both directions, time-reversed for backward
    {
        dim3 g(8, R, 2);
        k_gi<<<g, 256>>>(Wih_f, bih_f, Wih_b, bih_b);
    }
    // 8) reset barrier + zero h(0)
    k_init<<<17, 256>>>();
    // 9) persistent bidirectional GRU
    k_gru<<<128, 128>>>(Whh_f, bhh_f, Whh_b, bhh_b, out);
}

// round 3
// speedup vs baseline: 1.2275x; 1.2275x over previous
#include <cuda_runtime.h>
#include <math.h>

static const int B = 32;
static const int S = 512;
static const int R = 128;
static const int D = 64;
static const int E = 128;
static const int H = 256;
#define NROWS (32*512 + 128)   // B*S + R = 16512

typedef unsigned long long ull;

// ---------------- packed f32x2 helpers (sm_100+) ----------------------------
__device__ __forceinline__ ull fma2(ull a, ull b, ull c) {
    ull d; asm("fma.rn.f32x2 %0,%1,%2,%3;" : "=l"(d) : "l"(a), "l"(b), "l"(c));
    return d;
}
__device__ __forceinline__ ull add2(ull a, ull b) {
    ull d; asm("add.rn.f32x2 %0,%1,%2;" : "=l"(d) : "l"(a), "l"(b));
    return d;
}
__device__ __forceinline__ ull pk2(float x, float y) {
    ull d; asm("mov.b64 %0,{%1,%2};" : "=l"(d) : "f"(x), "f"(y));
    return d;
}
__device__ __forceinline__ float2 upk2(ull d) {
    float2 r; asm("mov.b64 {%0,%1},%2;" : "=f"(r.x), "=f"(r.y) : "l"(d));
    return r;
}

// ---------------- scratch (static device globals) ---------------------------
__device__ float g_emb[NROWS * 128];                 // (B*S + R, E)
__device__ float g_K[32 * 512 * 128];                // (B,S,E)
__device__ float g_Q[128 * 128];                     // (R,E)
__device__ float g_SC[32 * 128 * 512];               // scores -> exp(score-max)
__device__ float g_enc[32 * 128 * 64];               // (B,R,D)
__device__ float g_gi[2][128][768][32];              // [dir][t][row(3H)][batch]
__device__ float4 g_h[2][2][(256/4) * 32];           // [dir][parity][k4*32 + b]
__device__ int   g_bar[2];

// ---------------- 1) time embedding ----------------------------------------
__global__ void k_emb(const float* __restrict__ ts, const float* __restrict__ qt,
                      const float* __restrict__ w_per, const float* __restrict__ b_per,
                      const float* __restrict__ w_lin, const float* __restrict__ b_lin)
{
    int idx = blockIdx.x * blockDim.x + threadIdx.x;
    if (idx >= NROWS * 128) return;
    int row = idx >> 7;
    int e   = idx & 127;
    float t = (row < B * S) ? ts[row] : qt[row - B * S];
    float v;
    if (e == 0) v = fmaf(t, w_lin[0], b_lin[0]);
    else        v = sinf(fmaf(t, w_per[e - 1], b_per[e - 1]));
    g_emb[idx] = v;
}

// ---------------- 2) C = alpha*(A @ B^T) + bias, packed-fma version ---------
__global__ void __launch_bounds__(256)
k_gemm_nt(const float* __restrict__ Ag, const float* __restrict__ Bg,
          const float* __restrict__ bias, float* __restrict__ Cg,
          int Msz, int Nsz, int Ksz, int lda, int ldb, int ldc,
          long long strideA, long long strideB, long long strideC, float alpha)
{
    __shared__ float As[16][68];
    __shared__ float Bs[16][68];
    const float* A  = Ag + (long long)blockIdx.z * strideA;
    const float* Bm = Bg + (long long)blockIdx.z * strideB;
    float*       C  = Cg + (long long)blockIdx.z * strideC;
    int m0 = blockIdx.y * 64, n0 = blockIdx.x * 64;
    int tid = threadIdx.x;
    int tx = tid & 15, ty = tid >> 4;

    ull acc[4][2];
#pragma unroll
    for (int i = 0; i < 4; i++) { acc[i][0] = 0ull; acc[i][1] = 0ull; }

    for (int kc = 0; kc < Ksz; kc += 16) {
        int k = tid & 15;
        int v = tid >> 4;
#pragma unroll
        for (int p = 0; p < 4; p++) {
            As[k][v + p * 16] = A[(long long)(m0 + v + p * 16) * lda + kc + k];
            Bs[k][v + p * 16] = Bm[(long long)(n0 + v + p * 16) * ldb + kc + k];
        }
        __syncthreads();
#pragma unroll
        for (int kk = 0; kk < 16; kk++) {
            float4 a4 = *(const float4*)&As[kk][ty * 4];
            ulonglong2 bb = *(const ulonglong2*)&Bs[kk][tx * 4];
            ull aa;
            aa = pk2(a4.x, a4.x);
            acc[0][0] = fma2(aa, bb.x, acc[0][0]); acc[0][1] = fma2(aa, bb.y, acc[0][1]);
            aa = pk2(a4.y, a4.y);
            acc[1][0] = fma2(aa, bb.x, acc[1][0]); acc[1][1] = fma2(aa, bb.y, acc[1][1]);
            aa = pk2(a4.z, a4.z);
            acc[2][0] = fma2(aa, bb.x, acc[2][0]); acc[2][1] = fma2(aa, bb.y, acc[2][1]);
            aa = pk2(a4.w, a4.w);
            acc[3][0] = fma2(aa, bb.x, acc[3][0]); acc[3][1] = fma2(aa, bb.y, acc[3][1]);
        }
        __syncthreads();
    }
    float4 bv = make_float4(0.f, 0.f, 0.f, 0.f);
    if (bias) bv = *(const float4*)&bias[n0 + tx * 4];
#pragma unroll
    for (int i = 0; i < 4; i++) {
        int m = m0 + ty * 4 + i;
        float2 v0 = upk2(acc[i][0]), v1 = upk2(acc[i][1]);
        float4 o;
        o.x = fmaf(v0.x, alpha, bv.x);
        o.y = fmaf(v0.y, alpha, bv.y);
        o.z = fmaf(v1.x, alpha, bv.z);
        o.w = fmaf(v1.y, alpha, bv.w);
        *(float4*)&C[(long long)m * ldc + n0 + tx * 4] = o;
    }
}

// ---------------- 3) e = exp(score - rowmax) per (b,r) ----------------------
__global__ void k_exp()
{
    int row = blockIdx.x;
    float* p = g_SC + (long long)row * S;
    int tid = threadIdx.x;
    float v[4];
    float m = -3.402823466e38f;
#pragma unroll
    for (int i = 0; i < 4; i++) { v[i] = p[tid + i * 128]; m = fmaxf(m, v[i]); }
#pragma unroll
    for (int off = 16; off > 0; off >>= 1)
        m = fmaxf(m, __shfl_xor_sync(0xffffffffu, m, off));
    __shared__ float sm[4];
    if ((tid & 31) == 0) sm[tid >> 5] = m;
    __syncthreads();
    m = fmaxf(fmaxf(sm[0], sm[1]), fmaxf(sm[2], sm[3]));
#pragma unroll
    for (int i = 0; i < 4; i++) p[tid + i * 128] = expf(v[i] - m);
}

// ---------------- 4) enc_in = (e @ mask*x) / (e @ mask), packed -------------
__global__ void __launch_bounds__(256)
k_enc(const float* __restrict__ xv, const int* __restrict__ xm)
{
    __shared__ float Es[32][33];
    __shared__ float Xs[32][64];
    __shared__ float Ms[32][64];
    int b = blockIdx.x;
    int r0 = blockIdx.y * 32;
    int tid = threadIdx.x;
    int r  = tid >> 3;
    int d0 = (tid & 7) * 8;
    ull accN[4], accD[4];
#pragma unroll
    for (int i = 0; i < 4; i++) { accN[i] = 0ull; accD[i] = 0ull; }

    for (int sc = 0; sc < S; sc += 32) {
        {
            int ss = tid & 31, rr = tid >> 5;
#pragma unroll
            for (int p = 0; p < 4; p++)
                Es[rr + p * 8][ss] = g_SC[((long long)b * R + r0 + rr + p * 8) * S + sc + ss];
        }
        {
            int d = tid & 63, s0 = tid >> 6;
#pragma unroll
            for (int p = 0; p < 8; p++) {
                int ss = s0 + p * 4;
                long long gidx = ((long long)b * S + sc + ss) * D + d;
                int mk = xm[gidx];
                float x = xv[gidx];
                Xs[ss][d] = mk ? x : 0.f;
                Ms[ss][d] = mk ? 1.f : 0.f;
            }
        }
        __syncthreads();
#pragma unroll 4
        for (int ss = 0; ss < 32; ss++) {
            ull ee = pk2(Es[r][ss], Es[r][ss]);
            ulonglong2 X0 = *(const ulonglong2*)&Xs[ss][d0];
            ulonglong2 X1 = *(const ulonglong2*)&Xs[ss][d0 + 4];
            ulonglong2 M0 = *(const ulonglong2*)&Ms[ss][d0];
            ulonglong2 M1 = *(const ulonglong2*)&Ms[ss][d0 + 4];
            accN[0] = fma2(ee, X0.x, accN[0]);
            accN[1] = fma2(ee, X0.y, accN[1]);
            accN[2] = fma2(ee, X1.x, accN[2]);
            accN[3] = fma2(ee, X1.y, accN[3]);
            accD[0] = fma2(ee, M0.x, accD[0]);
            accD[1] = fma2(ee, M0.y, accD[1]);
            accD[2] = fma2(ee, M1.x, accD[2]);
            accD[3] = fma2(ee, M1.y, accD[3]);
        }
        __syncthreads();
    }
#pragma unroll
    for (int p = 0; p < 4; p++) {
        float2 n2 = upk2(accN[p]);
        float2 d2 = upk2(accD[p]);
        long long base = ((long long)b * R + r0 + r) * D + d0 + 2 * p;
        g_enc[base]     = n2.x / d2.x;
        g_enc[base + 1] = n2.y / d2.y;
    }
}

// ---------------- 5) gi[dir][t][row][b] = bih + enc[b][tsrc] . Wih[row] -----
__global__ void __launch_bounds__(256)
k_gi(const float* __restrict__ Wf, const float* __restrict__ bf,
     const float* __restrict__ Wb, const float* __restrict__ bb)
{
    int rc  = blockIdx.x * 96;
    int t   = blockIdx.y;
    int dir = blockIdx.z;
    const float* W  = dir ? Wb : Wf;
    const float* bi = dir ? bb : bf;
    int tsrc = dir ? (R - 1 - t) : t;

    __shared__ float encs[32][68];
    __shared__ float Ws[96][64];
    int tid = threadIdx.x;
    {
        int d = tid & 63, b0 = tid >> 6;
#pragma unroll
        for (int p = 0; p < 8; p++) {
            int b = b0 + p * 4;
            encs[b][d] = g_enc[((long long)b * R + tsrc) * D + d];
        }
    }
    {
        int d = tid & 63, r0 = tid >> 6;
#pragma unroll
        for (int p = 0; p < 24; p++) {
            int rl = r0 + p * 4;
            Ws[rl][d] = W[(long long)(rc + rl) * D + d];
        }
    }
    __syncthreads();
    int b  = tid & 31;
    int rg = tid >> 5;
    ull er[32];
#pragma unroll
    for (int i = 0; i < 16; i++) {
        ulonglong2 v = *(const ulonglong2*)&encs[b][i * 4];
        er[2 * i] = v.x; er[2 * i + 1] = v.y;
    }
#pragma unroll 2
    for (int q = 0; q < 12; q++) {
        int rl = rg * 12 + q;
        ull a0 = 0ull, a1 = 0ull;
#pragma unroll
        for (int i = 0; i < 16; i++) {
            ulonglong2 wv = *(const ulonglong2*)&Ws[rl][i * 4];
            a0 = fma2(wv.x, er[2 * i], a0);
            a1 = fma2(wv.y, er[2 * i + 1], a1);
        }
        float2 f0 = upk2(a0), f1 = upk2(a1);
        g_gi[dir][t][rc + rl][b] = f0.x + f0.y + f1.x + f1.y + bi[rc + rl];
    }
}

// ---------------- 6) init barrier + h(0)=0 ---------------------------------
__global__ void k_init()
{
    int tid = blockIdx.x * 256 + threadIdx.x;
    if (tid < 2) g_bar[tid] = 0;
    if (tid < 2 * 2048) {
        int dir = tid >> 11;
        int i = tid & 2047;
        g_h[dir][0][i] = make_float4(0.f, 0.f, 0.f, 0.f);
    }
}

// ---------------- 7) persistent bidirectional GRU (v2) ----------------------
// 128 CTAs (64/dir) x 256 threads. CTA owns 4 h-columns (12 Whh rows, SMEM).
// k-dim split across 8 warps; each warp streams its own h-slice straight from
// L2 (ld.cg), packed f32x2 FMAs, SMEM partial-sum reduction, flag barrier.
__global__ void __launch_bounds__(256, 1)
k_gru(const float* __restrict__ Whh_f, const float* __restrict__ bhh_f,
      const float* __restrict__ Whh_b, const float* __restrict__ bhh_b,
      float* __restrict__ out)
{
    int bid = blockIdx.x;
    int dir = bid >> 6;
    int grp = bid & 63;
    int j0  = grp * 4;
    const float* Whh = dir ? Whh_b : Whh_f;
    const float* bhh = dir ? bhh_b : bhh_f;
    int tid  = threadIdx.x;
    int w    = tid >> 5;   // warp 0..7 : k-slice; for tid<128 also = column
    int lane = tid & 31;   // batch

    __shared__ float4 Ws4[12][64];            // Whh slice, 12 KB
    __shared__ ull    part[8 * 12 * 32];      // partial sums, 24 KB

    for (int i = tid; i < 12 * 64; i += 256) {
        int row = i >> 6, k4 = i & 63;
        int g = row >> 2, c = row & 3;
        Ws4[row][k4] = ((const float4*)(Whh + (long long)(g * H + j0 + c) * H))[k4];
    }
    float br = 0.f, bz = 0.f, bn = 0.f, gir = 0.f, giz = 0.f, gin = 0.f;
    if (tid < 128) {
        br = bhh[0 * H + j0 + w];
        bz = bhh[1 * H + j0 + w];
        bn = bhh[2 * H + j0 + w];
        gir = __ldcg(&g_gi[dir][0][0 * H + j0 + w][lane]);
        giz = __ldcg(&g_gi[dir][0][1 * H + j0 + w][lane]);
        gin = __ldcg(&g_gi[dir][0][2 * H + j0 + w][lane]);
    }
    __syncthreads();

    volatile int* barp = (volatile int*)&g_bar[dir];

    for (int t = 0; t < R; t++) {
        int par = t & 1;
        const float4* hg = &g_h[dir][par][0];

        // --- accumulate over this warp's k-slice straight from L2 ----------
        ull acc[12];
#pragma unroll
        for (int rr = 0; rr < 12; rr++) acc[rr] = 0ull;
#pragma unroll
        for (int q = 0; q < 8; q++) {
            int k4 = w * 8 + q;
            float4 hv4 = __ldcg(&hg[k4 * 32 + lane]);
            ull h01 = pk2(hv4.x, hv4.y);
            ull h23 = pk2(hv4.z, hv4.w);
#pragma unroll
            for (int rr = 0; rr < 12; rr++) {
                ulonglong2 wv = *(const ulonglong2*)&Ws4[rr][k4];
                acc[rr] = fma2(wv.x, h01, acc[rr]);
                acc[rr] = fma2(wv.y, h23, acc[rr]);
            }
        }
        float hold = 0.f;
        if (tid < 128) {
            float4 h4 = __ldcg(&hg[grp * 32 + lane]);
            hold = (w == 0) ? h4.x : (w == 1) ? h4.y : (w == 2) ? h4.z : h4.w;
        }
        // --- partial sums to smem ------------------------------------------
#pragma unroll
        for (int rr = 0; rr < 12; rr++)
            part[w * 384 + rr * 32 + lane] = acc[rr];
        __syncthreads();

        // --- reduce + activation (threads 0..127; col = w) -----------------
        if (tid < 128) {
            ull sr = 0ull, sz = 0ull, sn = 0ull;
#pragma unroll
            for (int ww = 0; ww < 8; ww++) {
                sr = add2(sr, part[ww * 384 + (0 + w) * 32 + lane]);
                sz = add2(sz, part[ww * 384 + (4 + w) * 32 + lane]);
                sn = add2(sn, part[ww * 384 + (8 + w) * 32 + lane]);
            }
            float2 fr = upk2(sr), fz = upk2(sz), fn = upk2(sn);
            float ar = fr.x + fr.y, az = fz.x + fz.y, an = fn.x + fn.y;

            float rr = 1.f / (1.f + expf(-(gir + ar + br)));
            float zz = 1.f / (1.f + expf(-(giz + az + bz)));
            float nn = tanhf(gin + rr * (an + bn));
            float hn = (1.f - zz) * nn + zz * hold;

            int tout = dir ? (R - 1 - t) : t;
            out[((long long)lane * R + tout) * (2 * H) + dir * H + j0 + w] = hn;

            if (t < R - 1) {
                float* hw = (float*)&g_h[dir][par ^ 1][0];
                __stcg(hw + (grp * 32 + lane) * 4 + w, hn);
                // prefetch gi for t+1 while waiting on the barrier
                gir = __ldcg(&g_gi[dir][t + 1][0 * H + j0 + w][lane]);
                giz = __ldcg(&g_gi[dir][t + 1][1 * H + j0 + w][lane]);
                gin = __ldcg(&g_gi[dir][t + 1][2 * H + j0 + w][lane]);
            }
        }
        __syncthreads();   // protects part[] reuse AND h stores before fence

        if (t < R - 1) {
            if (tid == 0) {
                __threadfence();
                atomicAdd(&g_bar[dir], 1);
                int target = 64 * (t + 1);
                while (*barp < target) { }
            }
            __syncthreads();
        }
    }
}

// ---------------- launcher -------------------------------------------------
extern "C" void kernel_launch(void* const* d_in, const int* in_sizes, int n_in,
                              void* d_out, int out_size)
{
    const float* x_vals     = (const float*)d_in[0];
    const int*   x_mask     = (const int*)  d_in[1];
    const float* time_steps = (const float*)d_in[2];
    const float* query_t    = (const float*)d_in[3];
    const float* Wq         = (const float*)d_in[4];
    const float* bq         = (const float*)d_in[5];
    const float* Wk         = (const float*)d_in[6];
    const float* bk         = (const float*)d_in[7];
    const float* w_per      = (const float*)d_in[8];
    const float* b_per      = (const float*)d_in[9];
    const float* w_lin      = (const float*)d_in[10];
    const float* b_lin      = (const float*)d_in[11];
    const float* Wih_f      = (const float*)d_in[12];
    const float* Whh_f      = (const float*)d_in[13];
    const float* bih_f      = (const float*)d_in[14];
    const float* bhh_f      = (const float*)d_in[15];
    const float* Wih_b      = (const float*)d_in[16];
    const float* Whh_b      = (const float*)d_in[17];
    const float* bih_b      = (const float*)d_in[18];
    const float* bhh_b      = (const float*)d_in[19];
    float* out = (float*)d_out;

    float *p_emb, *p_K, *p_Q, *p_SC;
    cudaGetSymbolAddress((void**)&p_emb, g_emb);
    cudaGetSymbolAddress((void**)&p_K,   g_K);
    cudaGetSymbolAddress((void**)&p_Q,   g_Q);
    cudaGetSymbolAddress((void**)&p_SC,  g_SC);

    k_emb<<<(NROWS * 128 + 255) / 256, 256>>>(time_steps, query_t,
                                              w_per, b_per, w_lin, b_lin);
    {
        dim3 g(E / 64, (B * S) / 64, 1);
        k_gemm_nt<<<g, 256>>>(p_emb, Wk, bk, p_K, B * S, E, E, E, E, E,
                              0, 0, 0, 1.0f);
    }
    {
        dim3 g(E / 64, R / 64, 1);
        k_gemm_nt<<<g, 256>>>(p_emb + (long long)B * S * E, Wq, bq, p_Q,
                              R, E, E, E, E, E, 0, 0, 0, 1.0f);
    }
    {
        dim3 g(S / 64, R / 64, B);
        k_gemm_nt<<<g, 256>>>(p_Q, p_K, nullptr, p_SC, R, S, E, E, E, S,
                              0, (long long)S * E, (long long)R * S,
                              0.08838834764831845f);
    }
    k_exp<<<B * R, 128>>>();
    {
        dim3 g(B, R / 32);
        k_enc<<<g, 256>>>(x_vals, x_mask);
    }
    {
        dim3 g(8, R, 2);
        k_gi<<<g, 256>>>(Wih_f, bih_f, Wih_b, bih_b);
    }
    k_init<<<17, 256>>>();
    k_gru<<<128, 256>>>(Whh_f, bhh_f, Whh_b, bhh_b, out);
}

// round 5
// speedup vs baseline: 1.3500x; 1.0998x over previous
#include <cuda_runtime.h>
#include <math.h>

static const int B = 32;
static const int S = 512;
static const int R = 128;
static const int D = 64;
static const int E = 128;
static const int H = 256;
#define NROWS (32*512 + 128)   // B*S + R = 16512

typedef unsigned long long ull;

// ---------------- packed f32x2 helpers (sm_100+) ----------------------------
__device__ __forceinline__ ull fma2(ull a, ull b, ull c) {
    ull d; asm("fma.rn.f32x2 %0,%1,%2,%3;" : "=l"(d) : "l"(a), "l"(b), "l"(c));
    return d;
}
__device__ __forceinline__ ull add2(ull a, ull b) {
    ull d; asm("add.rn.f32x2 %0,%1,%2;" : "=l"(d) : "l"(a), "l"(b));
    return d;
}
__device__ __forceinline__ ull pk2(float x, float y) {
    ull d; asm("mov.b64 %0,{%1,%2};" : "=l"(d) : "f"(x), "f"(y));
    return d;
}
__device__ __forceinline__ float2 upk2(ull d) {
    float2 r; asm("mov.b64 {%0,%1},%2;" : "=f"(r.x), "=f"(r.y) : "l"(d));
    return r;
}
__device__ __forceinline__ void cp4(void* dst, const void* src) {
    unsigned d = (unsigned)__cvta_generic_to_shared(dst);
    asm volatile("cp.async.ca.shared.global [%0],[%1],4;" :: "r"(d), "l"(src));
}

// ---------------- scratch (static device globals) ---------------------------
__device__ float g_emb[NROWS * 128];                 // (B*S + R, E)
__device__ float g_K[32 * 512 * 128];                // (B,S,E)
__device__ float g_Q[128 * 128];                     // (R,E)
__device__ float g_SC[32 * 128 * 512];               // exp(scores), (B,R,S)
__device__ float g_enc[32 * 128 * 64];               // (B,R,D)
__device__ float g_gi[2][128][768][32];              // [dir][t][row(3H)][batch]
__device__ float4 g_h[2][2][(256/4) * 32];           // [dir][parity][k4*32 + b]
__device__ int   g_bar[2];                           // per-direction step counter

// ---------------- 1) time embedding + state init ----------------------------
__global__ void k_emb(const float* __restrict__ ts, const float* __restrict__ qt,
                      const float* __restrict__ w_per, const float* __restrict__ b_per,
                      const float* __restrict__ w_lin, const float* __restrict__ b_lin)
{
    int idx = blockIdx.x * blockDim.x + threadIdx.x;
    if (idx < 2048) {                       // zero h(0) for both dirs (parity 0)
        g_h[0][0][idx] = make_float4(0.f, 0.f, 0.f, 0.f);
        g_h[1][0][idx] = make_float4(0.f, 0.f, 0.f, 0.f);
    }
    if (idx < 2) g_bar[idx] = 0;
    if (idx >= NROWS * 128) return;
    int row = idx >> 7;
    int e   = idx & 127;
    float t = (row < B * S) ? ts[row] : qt[row - B * S];
    float v;
    if (e == 0) v = fmaf(t, w_lin[0], b_lin[0]);
    else        v = __sinf(fmaf(t, w_per[e - 1], b_per[e - 1]));
    g_emb[idx] = v;
}

// ---------------- 2) C = op(alpha*(A @ B^T) + bias), cp.async double-buffer --
// op = exp() when doexp. 64x64 tile, k-chunk 16, 256 threads.
__global__ void __launch_bounds__(256)
k_gemm_nt(const float* __restrict__ Ag, const float* __restrict__ Bg,
          const float* __restrict__ bias, float* __restrict__ Cg,
          int Ksz, int lda, int ldb, int ldc,
          long long strideA, long long strideB, long long strideC,
          float alpha, int doexp)
{
    __shared__ float As[2][16][68];
    __shared__ float Bs[2][16][68];
    const float* A  = Ag + (long long)blockIdx.z * strideA;
    const float* Bm = Bg + (long long)blockIdx.z * strideB;
    float*       C  = Cg + (long long)blockIdx.z * strideC;
    int m0 = blockIdx.y * 64, n0 = blockIdx.x * 64;
    int tid = threadIdx.x;
    int tx = tid & 15, ty = tid >> 4;
    int k = tid & 15, v = tid >> 4;

    ull acc[4][2];
#pragma unroll
    for (int i = 0; i < 4; i++) { acc[i][0] = 0ull; acc[i][1] = 0ull; }

    int nch = Ksz >> 4;
#pragma unroll
    for (int p = 0; p < 4; p++) {
        cp4(&As[0][k][v + p * 16], &A[(long long)(m0 + v + p * 16) * lda + k]);
        cp4(&Bs[0][k][v + p * 16], &Bm[(long long)(n0 + v + p * 16) * ldb + k]);
    }
    asm volatile("cp.async.commit_group;");

    for (int i = 0; i < nch; i++) {
        if (i + 1 < nch) {
            int buf = (i + 1) & 1, kc = (i + 1) * 16;
#pragma unroll
            for (int p = 0; p < 4; p++) {
                cp4(&As[buf][k][v + p * 16], &A[(long long)(m0 + v + p * 16) * lda + kc + k]);
                cp4(&Bs[buf][k][v + p * 16], &Bm[(long long)(n0 + v + p * 16) * ldb + kc + k]);
            }
            asm volatile("cp.async.commit_group;");
            asm volatile("cp.async.wait_group 1;");
        } else {
            asm volatile("cp.async.wait_group 0;");
        }
        __syncthreads();
        int cb = i & 1;
#pragma unroll
        for (int kk = 0; kk < 16; kk++) {
            float4 a4 = *(const float4*)&As[cb][kk][ty * 4];
            ulonglong2 bb = *(const ulonglong2*)&Bs[cb][kk][tx * 4];
            ull aa;
            aa = pk2(a4.x, a4.x);
            acc[0][0] = fma2(aa, bb.x, acc[0][0]); acc[0][1] = fma2(aa, bb.y, acc[0][1]);
            aa = pk2(a4.y, a4.y);
            acc[1][0] = fma2(aa, bb.x, acc[1][0]); acc[1][1] = fma2(aa, bb.y, acc[1][1]);
            aa = pk2(a4.z, a4.z);
            acc[2][0] = fma2(aa, bb.x, acc[2][0]); acc[2][1] = fma2(aa, bb.y, acc[2][1]);
            aa = pk2(a4.w, a4.w);
            acc[3][0] = fma2(aa, bb.x, acc[3][0]); acc[3][1] = fma2(aa, bb.y, acc[3][1]);
        }
        __syncthreads();
    }
    float4 bv = make_float4(0.f, 0.f, 0.f, 0.f);
    if (bias) bv = *(const float4*)&bias[n0 + tx * 4];
#pragma unroll
    for (int i = 0; i < 4; i++) {
        int m = m0 + ty * 4 + i;
        float2 v0 = upk2(acc[i][0]), v1 = upk2(acc[i][1]);
        float4 o;
        o.x = fmaf(v0.x, alpha, bv.x);
        o.y = fmaf(v0.y, alpha, bv.y);
        o.z = fmaf(v1.x, alpha, bv.z);
        o.w = fmaf(v1.y, alpha, bv.w);
        if (doexp) {
            o.x = __expf(o.x); o.y = __expf(o.y);
            o.z = __expf(o.z); o.w = __expf(o.w);
        }
        *(float4*)&C[(long long)m * ldc + n0 + tx * 4] = o;
    }
}

// ---------------- 3) enc_in = (e @ mask*x) / (e @ mask) ----------------------
// grid (B, R/16), 256 threads: thread = (r in 16, d-group of 4)
__global__ void __launch_bounds__(256)
k_enc(const float* __restrict__ xv, const int* __restrict__ xm)
{
    __shared__ float Es[16][33];
    __shared__ float Xs[32][64];
    __shared__ float Ms[32][64];
    int b = blockIdx.x;
    int r0 = blockIdx.y * 16;
    int tid = threadIdx.x;
    int r  = tid >> 4;
    int d0 = (tid & 15) * 4;
    ull accN[2] = {0ull, 0ull}, accD[2] = {0ull, 0ull};

    for (int sc = 0; sc < S; sc += 32) {
        {
            int ss = tid & 31, rr = tid >> 5;
#pragma unroll
            for (int p = 0; p < 2; p++)
                Es[rr + p * 8][ss] = g_SC[((long long)b * R + r0 + rr + p * 8) * S + sc + ss];
        }
        {
            int d = tid & 63, s0 = tid >> 6;
#pragma unroll
            for (int p = 0; p < 8; p++) {
                int ss = s0 + p * 4;
                long long gidx = ((long long)b * S + sc + ss) * D + d;
                int mk = xm[gidx];
                float x = xv[gidx];
                Xs[ss][d] = mk ? x : 0.f;
                Ms[ss][d] = mk ? 1.f : 0.f;
            }
        }
        __syncthreads();
#pragma unroll 4
        for (int ss = 0; ss < 32; ss++) {
            ull ee = pk2(Es[r][ss], Es[r][ss]);
            ulonglong2 X0 = *(const ulonglong2*)&Xs[ss][d0];
            ulonglong2 M0 = *(const ulonglong2*)&Ms[ss][d0];
            accN[0] = fma2(ee, X0.x, accN[0]);
            accN[1] = fma2(ee, X0.y, accN[1]);
            accD[0] = fma2(ee, M0.x, accD[0]);
            accD[1] = fma2(ee, M0.y, accD[1]);
        }
        __syncthreads();
    }
    float2 n0 = upk2(accN[0]), n1 = upk2(accN[1]);
    float2 dd0 = upk2(accD[0]), dd1 = upk2(accD[1]);
    float4 o;
    o.x = n0.x / dd0.x; o.y = n0.y / dd0.y;
    o.z = n1.x / dd1.x; o.w = n1.y / dd1.y;
    *(float4*)&g_enc[((long long)b * R + r0 + r) * D + d0] = o;
}

// ---------------- 4) gi[dir][t][row][b] = bih + enc[b][tsrc] . Wih[row] -----
__global__ void __launch_bounds__(256)
k_gi(const float* __restrict__ Wf, const float* __restrict__ bf,
     const float* __restrict__ Wb, const float* __restrict__ bb)
{
    int rc  = blockIdx.x * 96;
    int t   = blockIdx.y;
    int dir = blockIdx.z;
    const float* W  = dir ? Wb : Wf;
    const float* bi = dir ? bb : bf;
    int tsrc = dir ? (R - 1 - t) : t;

    __shared__ float encs[32][68];
    __shared__ float Ws[96][64];
    int tid = threadIdx.x;
    {
        int d = tid & 63, b0 = tid >> 6;
#pragma unroll
        for (int p = 0; p < 8; p++) {
            int b = b0 + p * 4;
            encs[b][d] = g_enc[((long long)b * R + tsrc) * D + d];
        }
    }
    {
        int d = tid & 63, r0 = tid >> 6;
#pragma unroll
        for (int p = 0; p < 24; p++) {
            int rl = r0 + p * 4;
            Ws[rl][d] = W[(long long)(rc + rl) * D + d];
        }
    }
    __syncthreads();
    int b  = tid & 31;
    int rg = tid >> 5;
    ull er[32];
#pragma unroll
    for (int i = 0; i < 16; i++) {
        ulonglong2 v = *(const ulonglong2*)&encs[b][i * 4];
        er[2 * i] = v.x; er[2 * i + 1] = v.y;
    }
#pragma unroll 2
    for (int q = 0; q < 12; q++) {
        int rl = rg * 12 + q;
        ull a0 = 0ull, a1 = 0ull;
#pragma unroll
        for (int i = 0; i < 16; i++) {
            ulonglong2 wv = *(const ulonglong2*)&Ws[rl][i * 4];
            a0 = fma2(wv.x, er[2 * i], a0);
            a1 = fma2(wv.y, er[2 * i + 1], a1);
        }
        float2 f0 = upk2(a0), f1 = upk2(a1);
        g_gi[dir][t][rc + rl][b] = f0.x + f0.y + f1.x + f1.y + bi[rc + rl];
    }
}

// ---------------- 5) persistent bidirectional GRU (proven atomic barrier) ---
// 128 CTAs (64/dir) x 256 threads. CTA owns 4 h-columns (12 Whh rows, SMEM).
// k-dim split across 8 warps; each warp streams its own h-slice straight from
// L2 (ld.cg), packed f32x2 FMAs, SMEM partial-sum reduction, atomic barrier.
__global__ void __launch_bounds__(256, 1)
k_gru(const float* __restrict__ Whh_f, const float* __restrict__ bhh_f,
      const float* __restrict__ Whh_b, const float* __restrict__ bhh_b,
      float* __restrict__ out)
{
    int bid = blockIdx.x;
    int dir = bid >> 6;
    int grp = bid & 63;
    int j0  = grp * 4;
    const float* Whh = dir ? Whh_b : Whh_f;
    const float* bhh = dir ? bhh_b : bhh_f;
    int tid  = threadIdx.x;
    int w    = tid >> 5;   // warp 0..7 : k-slice; for tid<128 also = column
    int lane = tid & 31;   // batch

    __shared__ float4 Ws4[12][64];            // Whh slice, 12 KB
    __shared__ ull    part[8 * 12 * 32];      // partial sums, 24 KB

    for (int i = tid; i < 12 * 64; i += 256) {
        int row = i >> 6, k4 = i & 63;
        int g = row >> 2, c = row & 3;
        Ws4[row][k4] = ((const float4*)(Whh + (long long)(g * H + j0 + c) * H))[k4];
    }
    float br = 0.f, bz = 0.f, bn = 0.f, gir = 0.f, giz = 0.f, gin = 0.f;
    if (tid < 128) {
        br = bhh[0 * H + j0 + w];
        bz = bhh[1 * H + j0 + w];
        bn = bhh[2 * H + j0 + w];
        gir = __ldcg(&g_gi[dir][0][0 * H + j0 + w][lane]);
        giz = __ldcg(&g_gi[dir][0][1 * H + j0 + w][lane]);
        gin = __ldcg(&g_gi[dir][0][2 * H + j0 + w][lane]);
    }
    __syncthreads();

    volatile int* barp = (volatile int*)&g_bar[dir];

    for (int t = 0; t < R; t++) {
        int par = t & 1;
        const float4* hg = &g_h[dir][par][0];

        // --- accumulate over this warp's k-slice straight from L2 ----------
        ull acc[12];
#pragma unroll
        for (int rr = 0; rr < 12; rr++) acc[rr] = 0ull;
#pragma unroll
        for (int q = 0; q < 8; q++) {
            int k4 = w * 8 + q;
            float4 hv4 = __ldcg(&hg[k4 * 32 + lane]);
            ull h01 = pk2(hv4.x, hv4.y);
            ull h23 = pk2(hv4.z, hv4.w);
#pragma unroll
            for (int rr = 0; rr < 12; rr++) {
                ulonglong2 wv = *(const ulonglong2*)&Ws4[rr][k4];
                acc[rr] = fma2(wv.x, h01, acc[rr]);
                acc[rr] = fma2(wv.y, h23, acc[rr]);
            }
        }
        float hold = 0.f;
        if (tid < 128) {
            float4 h4 = __ldcg(&hg[grp * 32 + lane]);
            hold = (w == 0) ? h4.x : (w == 1) ? h4.y : (w == 2) ? h4.z : h4.w;
        }
#pragma unroll
        for (int rr = 0; rr < 12; rr++)
            part[w * 384 + rr * 32 + lane] = acc[rr];
        __syncthreads();

        // --- reduce + activation (threads 0..127; col = w) -----------------
        if (tid < 128) {
            ull sr = 0ull, sz = 0ull, sn = 0ull;
#pragma unroll
            for (int ww = 0; ww < 8; ww++) {
                sr = add2(sr, part[ww * 384 + (0 + w) * 32 + lane]);
                sz = add2(sz, part[ww * 384 + (4 + w) * 32 + lane]);
                sn = add2(sn, part[ww * 384 + (8 + w) * 32 + lane]);
            }
            float2 fr = upk2(sr), fz = upk2(sz), fn = upk2(sn);
            float ar = fr.x + fr.y, az = fz.x + fz.y, an = fn.x + fn.y;

            float rr = 1.f / (1.f + expf(-(gir + ar + br)));
            float zz = 1.f / (1.f + expf(-(giz + az + bz)));
            float nn = tanhf(gin + rr * (an + bn));
            float hn = (1.f - zz) * nn + zz * hold;

            int tout = dir ? (R - 1 - t) : t;
            out[((long long)lane * R + tout) * (2 * H) + dir * H + j0 + w] = hn;

            if (t < R - 1) {
                float* hw = (float*)&g_h[dir][par ^ 1][0];
                __stcg(hw + (grp * 32 + lane) * 4 + w, hn);
                // prefetch gi for t+1 while waiting on the barrier
                gir = __ldcg(&g_gi[dir][t + 1][0 * H + j0 + w][lane]);
                giz = __ldcg(&g_gi[dir][t + 1][1 * H + j0 + w][lane]);
                gin = __ldcg(&g_gi[dir][t + 1][2 * H + j0 + w][lane]);
            }
        }
        __syncthreads();   // h stores done block-wide; part[] safe for reuse

        if (t < R - 1) {
            if (tid == 0) {
                __threadfence();
                atomicAdd(&g_bar[dir], 1);
                int target = 64 * (t + 1);
                while (*barp < target) { }
            }
            __syncthreads();
        }
    }
}

// ---------------- launcher -------------------------------------------------
extern "C" void kernel_launch(void* const* d_in, const int* in_sizes, int n_in,
                              void* d_out, int out_size)
{
    const float* x_vals     = (const float*)d_in[0];
    const int*   x_mask     = (const int*)  d_in[1];
    const float* time_steps = (const float*)d_in[2];
    const float* query_t    = (const float*)d_in[3];
    const float* Wq         = (const float*)d_in[4];
    const float* bq         = (const float*)d_in[5];
    const float* Wk         = (const float*)d_in[6];
    const float* bk         = (const float*)d_in[7];
    const float* w_per      = (const float*)d_in[8];
    const float* b_per      = (const float*)d_in[9];
    const float* w_lin      = (const float*)d_in[10];
    const float* b_lin      = (const float*)d_in[11];
    const float* Wih_f      = (const float*)d_in[12];
    const float* Whh_f      = (const float*)d_in[13];
    const float* bih_f      = (const float*)d_in[14];
    const float* bhh_f      = (const float*)d_in[15];
    const float* Wih_b      = (const float*)d_in[16];
    const float* Whh_b      = (const float*)d_in[17];
    const float* bih_b      = (const float*)d_in[18];
    const float* bhh_b      = (const float*)d_in[19];
    float* out = (float*)d_out;

    float *p_emb, *p_K, *p_Q, *p_SC;
    cudaGetSymbolAddress((void**)&p_emb, g_emb);
    cudaGetSymbolAddress((void**)&p_K,   g_K);
    cudaGetSymbolAddress((void**)&p_Q,   g_Q);
    cudaGetSymbolAddress((void**)&p_SC,  g_SC);

    // 1) embeddings (+ h/barrier init)
    k_emb<<<(NROWS * 128 + 255) / 256, 256>>>(time_steps, query_t,
                                              w_per, b_per, w_lin, b_lin);
    // 2) K = emb_k @ Wk^T + bk
    {
        dim3 g(E / 64, (B * S) / 64, 1);
        k_gemm_nt<<<g, 256>>>(p_emb, Wk, bk, p_K, E, E, E, E,
                              0, 0, 0, 1.0f, 0);
    }
    // 3) Q = emb_q @ Wq^T + bq
    {
        dim3 g(E / 64, R / 64, 1);
        k_gemm_nt<<<g, 256>>>(p_emb + (long long)B * S * E, Wq, bq, p_Q,
                              E, E, E, E, 0, 0, 0, 1.0f, 0);
    }
    // 4) SC[b] = exp(Q @ K_b^T / sqrt(E))   (exp fused; scores are O(1))
    {
        dim3 g(S / 64, R / 64, B);
        k_gemm_nt<<<g, 256>>>(p_Q, p_K, nullptr, p_SC, E, E, E, S,
                              0, (long long)S * E, (long long)R * S,
                              0.08838834764831845f, 1);
    }
    // 5) enc_in = (e @ mx) / (e @ m)
    {
        dim3 g(B, R / 16);
        k_enc<<<g, 256>>>(x_vals, x_mask);
    }
    // 6) gi for both directions (backward pre-reversed)
    {
        dim3 g(8, R, 2);
        k_gi<<<g, 256>>>(Wih_f, bih_f, Wih_b, bih_b);
    }
    // 7) persistent bidirectional GRU
    k_gru<<<128, 256>>>(Whh_f, bhh_f, Whh_b, bhh_b, out);
}